// round 11
// baseline (speedup 1.0000x reference)
#include <cuda_runtime.h>

typedef unsigned long long ull;

#define Hh    64
#define Gg    192
#define Tt    512
#define Bb    4096
#define BT    32      // batch per CTA
#define NCTA  128     // 128 * 32 = 4096
#define NTHR  384     // 12 warps; 4 independent 96-thread batch-groups
#define PAD_H 40      // k-major h row stride: =8 mod 32 -> CF gate-phase access, 16B-aligned rows
#define PAD_S 196     // S1 row stride: =4 mod 32 -> CF gate-phase reads
#define PAD_N 68      // S2n row stride: =4 mod 32

struct __align__(16) Smem {
    float Wt0 [Hh][Gg];    // Whh0^T (k-major)
    float Wt1i[Hh][Gg];    // Wih1^T
    float Wt1h[Hh][Gg];    // Whh1^T
    float hT0[Hh][PAD_H];  // h0 transposed: hT0[k][b]
    float hT1[Hh][PAD_H];
    float S1 [BT][PAD_S];  // gate pre-activations [b][g]
    float S2n[BT][PAD_N];  // layer-1 hg_n (needs separate r* multiply)
    float bhh0[Gg], bih0[Gg], bih1[Gg], bhh1[Gg];
    float Wih0c[Gg][2];
    float Wp_s[2*Hh];
    float xbuf[2][BT][2];  // double-buffered x_t
    float bp_s;
};

__device__ __forceinline__ ull dup2(float a) {
    ull r; asm("mov.b64 %0, {%1, %1};" : "=l"(r) : "f"(a)); return r;
}
__device__ __forceinline__ void upk2(ull v, float& lo, float& hi) {
    asm("mov.b64 {%0, %1}, %2;" : "=f"(lo), "=f"(hi) : "l"(v));
}
// packed fp32x2 FMA: d = a*b + d  (2 FMA per instruction -> 128 FMA/cyc/SM)
__device__ __forceinline__ void fma2(ull& d, ull a, ull b) {
    asm("fma.rn.f32x2 %0, %1, %2, %0;" : "+l"(d) : "l"(a), "l"(b));
}

__device__ __forceinline__ float sigm(float x) {
    // graceful at +-inf: exp->inf -> 0, exp->0 -> 1
    return __fdividef(1.0f, 1.0f + __expf(-x));
}
__device__ __forceinline__ float tanh_(float x) {
    // 1 - 2/(exp(2x)+1): graceful saturation at +-1
    return 1.0f - __fdividef(2.0f, __expf(2.0f * x) + 1.0f);
}

// 96-thread group barrier (ids 1..4)
__device__ __forceinline__ void gbar(int id) {
    asm volatile("bar.sync %0, 96;" :: "r"(id) : "memory");
}

__global__ void __launch_bounds__(NTHR, 1) gru2_kernel(
    const float* __restrict__ x,
    const float* __restrict__ Wih0, const float* __restrict__ Whh0,
    const float* __restrict__ bih0, const float* __restrict__ bhh0,
    const float* __restrict__ Wih1, const float* __restrict__ Whh1,
    const float* __restrict__ bih1, const float* __restrict__ bhh1,
    const float* __restrict__ Wp,   const float* __restrict__ bp,
    float* __restrict__ out)
{
    extern __shared__ char smraw[];
    Smem* s = reinterpret_cast<Smem*>(smraw);
    const int tid = threadIdx.x;
    const int b0  = blockIdx.x * BT;

    // ---- one-time: stage weights (transposed to k-major), biases, zero state ----
    for (int idx = tid; idx < Gg * Hh; idx += NTHR) {
        int g = idx / Hh, k = idx - g * Hh;
        s->Wt0 [k][g] = Whh0[idx];
        s->Wt1i[k][g] = Wih1[idx];
        s->Wt1h[k][g] = Whh1[idx];
    }
    for (int idx = tid; idx < Gg; idx += NTHR) {
        s->bhh0[idx] = bhh0[idx];
        s->bih0[idx] = bih0[idx];
        s->bih1[idx] = bih1[idx];
        s->bhh1[idx] = bhh1[idx];
        s->Wih0c[idx][0] = Wih0[idx * 2 + 0];
        s->Wih0c[idx][1] = Wih0[idx * 2 + 1];
    }
    for (int idx = tid; idx < 2 * Hh; idx += NTHR) s->Wp_s[idx] = Wp[idx];
    if (tid == 0) s->bp_s = bp[0];
    for (int idx = tid; idx < Hh * PAD_H; idx += NTHR) {
        (&s->hT0[0][0])[idx] = 0.0f;
        (&s->hT1[0][0])[idx] = 0.0f;
    }
    if (tid < 2 * BT) ((float*)s->xbuf[0])[tid] = x[(0 * Bb + b0) * 2 + tid];
    __syncthreads();

    // thread tile: 4 independent 96-thread groups, one per 8-batch slice.
    // Within a group, thread -> gate pair gp (96 pairs = 192 gates).
    const int bq   = tid / 96;       // batch group 0..3 (uniform per warp: 96 = 3 warps)
    const int gp   = tid - 96 * bq;  // 0..95
    const int barid = bq + 1;
    const int g0   = 2 * gp;
    const float* w0  = &s->Wt0 [0][g0];
    const float* w1i = &s->Wt1i[0][g0];
    const float* w1h = &s->Wt1h[0][g0];
    const float* h0r = &s->hT0[0][8 * bq];
    const float* h1r = &s->hT1[0][8 * bq];

    // loop-invariant packed biases (hoisted out of the t-loop)
    const ull pb0  = dup2(s->bhh0[g0]), pb1  = dup2(s->bhh0[g0 + 1]);
    const ull pbx0 = dup2(s->bih1[g0]), pbx1 = dup2(s->bih1[g0 + 1]);
    const ull pbh0 = dup2(s->bhh1[g0]), pbh1 = dup2(s->bhh1[g0 + 1]);

    for (int t = 0; t < Tt; t++) {
        // per-group prefetch of next step's x slice (16 floats per group)
        float xreg = 0.0f;
        if (gp < 16 && t + 1 < Tt)
            xreg = x[((t + 1) * Bb + b0 + 8 * bq) * 2 + gp];

        // ---- Phase A: S1[b][g] = bhh0[g] + sum_k Whh0[g][k] * h0[b][k] ----
        {
            ull a0[4], a1[4];
            #pragma unroll
            for (int p = 0; p < 4; p++) { a0[p] = pb0; a1[p] = pb1; }
            #pragma unroll 8
            for (int k = 0; k < Hh; k++) {
                float2 wv = *(const float2*)(w0 + k * Gg);
                ull wp0 = dup2(wv.x), wp1 = dup2(wv.y);
                ulonglong2 ha = *(const ulonglong2*)(h0r + k * PAD_H);
                ulonglong2 hb = *(const ulonglong2*)(h0r + k * PAD_H + 4);
                fma2(a0[0], wp0, ha.x); fma2(a1[0], wp1, ha.x);
                fma2(a0[1], wp0, ha.y); fma2(a1[1], wp1, ha.y);
                fma2(a0[2], wp0, hb.x); fma2(a1[2], wp1, hb.x);
                fma2(a0[3], wp0, hb.y); fma2(a1[3], wp1, hb.y);
            }
            #pragma unroll
            for (int p = 0; p < 4; p++) {
                float l0, h0v, l1, h1v;
                upk2(a0[p], l0, h0v); upk2(a1[p], l1, h1v);
                int b = 8 * bq + 2 * p;
                *(float2*)&s->S1[b    ][g0] = make_float2(l0,  l1);
                *(float2*)&s->S1[b + 1][g0] = make_float2(h0v, h1v);
            }
        }
        if (gp < 16 && t + 1 < Tt)
            ((float*)s->xbuf[(t + 1) & 1][8 * bq])[gp] = xreg;
        gbar(barid);

        // ---- Phase B: layer-0 gates, h0 updated in place (batch-fast lanes) ----
        {
            const float* xb = (const float*)s->xbuf[t & 1];
            for (int u = gp; u < 8 * Hh; u += 96) {
                int bl = u & 7, j = u >> 3;        // lanes: b fast -> CF h access
                int b = 8 * bq + bl;
                float x0 = xb[b * 2], x1 = xb[b * 2 + 1];
                float2 wr = *(const float2*)&s->Wih0c[j      ][0];
                float2 wz = *(const float2*)&s->Wih0c[j +  64][0];
                float2 wn = *(const float2*)&s->Wih0c[j + 128][0];
                float xr = fmaf(wr.x, x0, fmaf(wr.y, x1, s->bih0[j      ]));
                float xz = fmaf(wz.x, x0, fmaf(wz.y, x1, s->bih0[j +  64]));
                float xn = fmaf(wn.x, x0, fmaf(wn.y, x1, s->bih0[j + 128]));
                float r = sigm(xr + s->S1[b][j]);
                float z = sigm(xz + s->S1[b][j + 64]);
                float n = tanh_(fmaf(r, s->S1[b][j + 128], xn));
                float hOld = s->hT0[j][b];
                s->hT0[j][b] = n + z * (hOld - n);
            }
        }
        gbar(barid);

        // ---- Phase C: fused layer-1 matvecs (Wih1@h0new and Whh1@h1) ----
        {
            ull ax0[4], ax1[4], ah0[4], ah1[4];
            #pragma unroll
            for (int p = 0; p < 4; p++) {
                ax0[p] = pbx0; ax1[p] = pbx1; ah0[p] = pbh0; ah1[p] = pbh1;
            }
            #pragma unroll 4
            for (int k = 0; k < Hh; k++) {
                float2 wa = *(const float2*)(w1i + k * Gg);
                float2 wb = *(const float2*)(w1h + k * Gg);
                ull wa0 = dup2(wa.x), wa1 = dup2(wa.y);
                ull wb0 = dup2(wb.x), wb1 = dup2(wb.y);
                ulonglong2 h0a = *(const ulonglong2*)(h0r + k * PAD_H);
                ulonglong2 h0b = *(const ulonglong2*)(h0r + k * PAD_H + 4);
                ulonglong2 h1a = *(const ulonglong2*)(h1r + k * PAD_H);
                ulonglong2 h1b = *(const ulonglong2*)(h1r + k * PAD_H + 4);
                fma2(ax0[0], wa0, h0a.x); fma2(ax1[0], wa1, h0a.x);
                fma2(ax0[1], wa0, h0a.y); fma2(ax1[1], wa1, h0a.y);
                fma2(ax0[2], wa0, h0b.x); fma2(ax1[2], wa1, h0b.x);
                fma2(ax0[3], wa0, h0b.y); fma2(ax1[3], wa1, h0b.y);
                fma2(ah0[0], wb0, h1a.x); fma2(ah1[0], wb1, h1a.x);
                fma2(ah0[1], wb0, h1a.y); fma2(ah1[1], wb1, h1a.y);
                fma2(ah0[2], wb0, h1b.x); fma2(ah1[2], wb1, h1b.x);
                fma2(ah0[3], wb0, h1b.y); fma2(ah1[3], wb1, h1b.y);
            }
            #pragma unroll
            for (int p = 0; p < 4; p++) {
                int b = 8 * bq + 2 * p;
                float xl0, xh0, xl1, xh1, hl0, hh0, hl1, hh1;
                upk2(ax0[p], xl0, xh0); upk2(ax1[p], xl1, xh1);
                upk2(ah0[p], hl0, hh0); upk2(ah1[p], hl1, hh1);
                if (gp < 64) {  // r,z gates: x-side + h-side fold together
                    *(float2*)&s->S1[b    ][g0] = make_float2(xl0 + hl0, xl1 + hl1);
                    *(float2*)&s->S1[b + 1][g0] = make_float2(xh0 + hh0, xh1 + hh1);
                } else {        // n gate: keep hg_n separate (r * hg_n)
                    *(float2*)&s->S1[b    ][g0] = make_float2(xl0, xl1);
                    *(float2*)&s->S1[b + 1][g0] = make_float2(xh0, xh1);
                    *(float2*)&s->S2n[b    ][g0 - 128] = make_float2(hl0, hl1);
                    *(float2*)&s->S2n[b + 1][g0 - 128] = make_float2(hh0, hh1);
                }
            }
        }
        gbar(barid);

        // ---- Phase D: layer-1 gates, h1 updated in place (batch-fast lanes) ----
        for (int u = gp; u < 8 * Hh; u += 96) {
            int bl = u & 7, j = u >> 3;
            int b = 8 * bq + bl;
            float r = sigm(s->S1[b][j]);
            float z = sigm(s->S1[b][j + 64]);
            float n = tanh_(fmaf(r, s->S2n[b][j], s->S1[b][j + 128]));
            float hOld = s->hT1[j][b];
            s->hT1[j][b] = n + z * (hOld - n);
        }
        gbar(barid);
    }

    __syncthreads();

    // ---- final projection: out[b] = bp + Wp . [h0_final, h1_final] ----
    if (tid < BT) {
        float acc = s->bp_s;
        #pragma unroll
        for (int j = 0; j < Hh; j++) acc = fmaf(s->Wp_s[j],      s->hT0[j][tid], acc);
        #pragma unroll
        for (int j = 0; j < Hh; j++) acc = fmaf(s->Wp_s[64 + j], s->hT1[j][tid], acc);
        out[b0 + tid] = acc;
    }
}

extern "C" void kernel_launch(void* const* d_in, const int* in_sizes, int n_in,
                              void* d_out, int out_size)
{
    const float* x    = (const float*)d_in[0];
    const float* Wih0 = (const float*)d_in[1];
    const float* Whh0 = (const float*)d_in[2];
    const float* bih0 = (const float*)d_in[3];
    const float* bhh0 = (const float*)d_in[4];
    const float* Wih1 = (const float*)d_in[5];
    const float* Whh1 = (const float*)d_in[6];
    const float* bih1 = (const float*)d_in[7];
    const float* bhh1 = (const float*)d_in[8];
    const float* Wp   = (const float*)d_in[9];
    const float* bp   = (const float*)d_in[10];
    float* out = (float*)d_out;

    cudaFuncSetAttribute(gru2_kernel,
                         cudaFuncAttributeMaxDynamicSharedMemorySize,
                         (int)sizeof(Smem));
    gru2_kernel<<<NCTA, NTHR, sizeof(Smem)>>>(
        x, Wih0, Whh0, bih0, bhh0, Wih1, Whh1, bih1, bhh1, Wp, bp, out);
}

// round 15
// speedup vs baseline: 1.1120x; 1.1120x over previous
#include <cuda_runtime.h>

typedef unsigned long long ull;

#define Hh    64
#define Gg    192
#define Tt    512
#define Bb    4096
#define BT    32      // batch per CTA
#define NCTA  128
#define NTHR  256     // 8 warps; 4 groups of 64 threads (2 warps each)
#define PAD_H 36      // h row stride: 144B rows, 16B-aligned; 4-way on j-row access (accepted)

struct __align__(16) Smem {
    float Wt0 [Hh][Gg];      // Whh0^T (k-major)
    float Wt1i[Hh][Gg];      // Wih1^T
    float Wt1h[Hh][Gg];      // Whh1^T
    float h0[2][Hh][PAD_H];  // double-buffered layer-0 state, [buf][k][b]
    float h1[2][Hh][PAD_H];  // double-buffered layer-1 state
    float xbuf[2][BT][2];    // double-buffered x_t
};

__device__ __forceinline__ ull dup2(float a) {
    ull r; asm("mov.b64 %0, {%1, %1};" : "=l"(r) : "f"(a)); return r;
}
__device__ __forceinline__ void upk2(ull v, float& lo, float& hi) {
    asm("mov.b64 {%0, %1}, %2;" : "=f"(lo), "=f"(hi) : "l"(v));
}
// packed fp32x2 FMA: d = a*b + d
__device__ __forceinline__ void fma2(ull& d, ull a, ull b) {
    asm("fma.rn.f32x2 %0, %1, %2, %0;" : "+l"(d) : "l"(a), "l"(b));
}
__device__ __forceinline__ float sigm(float x) {
    return __fdividef(1.0f, 1.0f + __expf(-x));
}
__device__ __forceinline__ float tanh_(float x) {
    return 1.0f - __fdividef(2.0f, __expf(2.0f * x) + 1.0f);
}
// 64-thread group barrier (ids 1..4)
__device__ __forceinline__ void gbar(int id) {
    asm volatile("bar.sync %0, 64;" :: "r"(id) : "memory");
}

__global__ void __launch_bounds__(NTHR, 1) gru2_kernel(
    const float* __restrict__ x,
    const float* __restrict__ Wih0, const float* __restrict__ Whh0,
    const float* __restrict__ bih0, const float* __restrict__ bhh0,
    const float* __restrict__ Wih1, const float* __restrict__ Whh1,
    const float* __restrict__ bih1, const float* __restrict__ bhh1,
    const float* __restrict__ Wp,   const float* __restrict__ bp,
    float* __restrict__ out)
{
    extern __shared__ char smraw[];
    Smem* s = reinterpret_cast<Smem*>(smraw);
    const int tid = threadIdx.x;
    const int b0  = blockIdx.x * BT;

    // ---- stage weights k-major; zero both h buffers; preload x_0 ----
    for (int idx = tid; idx < Gg * Hh; idx += NTHR) {
        int g = idx >> 6, k = idx & 63;
        s->Wt0 [k][g] = Whh0[idx];
        s->Wt1i[k][g] = Wih1[idx];
        s->Wt1h[k][g] = Whh1[idx];
    }
    for (int idx = tid; idx < 2 * 2 * Hh * PAD_H; idx += NTHR)
        (&s->h0[0][0][0])[idx] = 0.0f;   // h0 and h1 are contiguous
    if (tid < 2 * BT) (&s->xbuf[0][0][0])[tid] = x[(0 * Bb + b0) * 2 + tid];
    __syncthreads();

    // thread tile: 4 independent 64-thread groups (8 batches each);
    // thread = gate triple (j, j+64, j+128) x 8 batches
    const int bq    = tid >> 6;      // group 0..3
    const int j     = tid & 63;      // 0..63
    const int barid = bq + 1;
    const int bb    = 8 * bq;        // batch base within CTA

    // per-thread constants cached in registers for the whole kernel
    const float wxr0 = Wih0[2*j],        wxr1 = Wih0[2*j+1];
    const float wxz0 = Wih0[2*(j+64)],   wxz1 = Wih0[2*(j+64)+1];
    const float wxn0 = Wih0[2*(j+128)],  wxn1 = Wih0[2*(j+128)+1];
    const float bxr = bih0[j], bxz = bih0[j+64], bxn = bih0[j+128];
    const float bhr = bhh0[j], bhz = bhh0[j+64], bhn = bhh0[j+128];
    const float cxr = bih1[j], cxz = bih1[j+64], cxn = bih1[j+128];
    const float chr = bhh1[j], chz = bhh1[j+64], chn = bhh1[j+128];

    for (int t = 0; t < Tt; t++) {
        const int cur = t & 1, nxt = cur ^ 1;

        float xreg = 0.0f;
        if (j < 16 && t + 1 < Tt)
            xreg = x[((t + 1) * Bb + b0 + bb) * 2 + j];

        // ---- A': Whh0 @ h0[cur] for 3 gates x 8 batches, then layer-0 gates in regs ----
        {
            ull aR[4], aZ[4], aN[4];
            {
                ull pr = dup2(bhr), pz = dup2(bhz), pn = dup2(bhn);
                #pragma unroll
                for (int p = 0; p < 4; p++) { aR[p] = pr; aZ[p] = pz; aN[p] = pn; }
            }
            #pragma unroll 8
            for (int k = 0; k < Hh; k++) {
                ull wr = dup2(s->Wt0[k][j]);
                ull wz = dup2(s->Wt0[k][j + 64]);
                ull wn = dup2(s->Wt0[k][j + 128]);
                ulonglong2 ha = *(const ulonglong2*)&s->h0[cur][k][bb];
                ulonglong2 hb = *(const ulonglong2*)&s->h0[cur][k][bb + 4];
                fma2(aR[0], wr, ha.x); fma2(aR[1], wr, ha.y);
                fma2(aR[2], wr, hb.x); fma2(aR[3], wr, hb.y);
                fma2(aZ[0], wz, ha.x); fma2(aZ[1], wz, ha.y);
                fma2(aZ[2], wz, hb.x); fma2(aZ[3], wz, hb.y);
                fma2(aN[0], wn, ha.x); fma2(aN[1], wn, ha.y);
                fma2(aN[2], wn, hb.x); fma2(aN[3], wn, hb.y);
            }
            // old h0 for the z-blend (own row j)
            ulonglong2 hoa = *(const ulonglong2*)&s->h0[cur][j][bb];
            ulonglong2 hob = *(const ulonglong2*)&s->h0[cur][j][bb + 4];
            ull hold[4] = { hoa.x, hoa.y, hob.x, hob.y };
            float hnew[8];
            #pragma unroll
            for (int p = 0; p < 4; p++) {
                float4 xq = *(const float4*)&s->xbuf[cur][bb + 2 * p][0];
                float sr0, sr1, sz0, sz1, sn0, sn1, ho0, ho1;
                upk2(aR[p], sr0, sr1); upk2(aZ[p], sz0, sz1);
                upk2(aN[p], sn0, sn1); upk2(hold[p], ho0, ho1);
                float xr0 = fmaf(wxr0, xq.x, fmaf(wxr1, xq.y, bxr));
                float xz0 = fmaf(wxz0, xq.x, fmaf(wxz1, xq.y, bxz));
                float xn0 = fmaf(wxn0, xq.x, fmaf(wxn1, xq.y, bxn));
                float xr1 = fmaf(wxr0, xq.z, fmaf(wxr1, xq.w, bxr));
                float xz1 = fmaf(wxz0, xq.z, fmaf(wxz1, xq.w, bxz));
                float xn1 = fmaf(wxn0, xq.z, fmaf(wxn1, xq.w, bxn));
                float r0 = sigm(xr0 + sr0), z0 = sigm(xz0 + sz0);
                float n0 = tanh_(fmaf(r0, sn0, xn0));
                float r1 = sigm(xr1 + sr1), z1 = sigm(xz1 + sz1);
                float n1 = tanh_(fmaf(r1, sn1, xn1));
                hnew[2*p]     = n0 + z0 * (ho0 - n0);
                hnew[2*p + 1] = n1 + z1 * (ho1 - n1);
            }
            *(float4*)&s->h0[nxt][j][bb]     = make_float4(hnew[0], hnew[1], hnew[2], hnew[3]);
            *(float4*)&s->h0[nxt][j][bb + 4] = make_float4(hnew[4], hnew[5], hnew[6], hnew[7]);
        }
        if (j < 16 && t + 1 < Tt)
            (&s->xbuf[nxt][bb][0])[j] = xreg;
        gbar(barid);

        // ---- C': Wih1 @ h0[nxt] + Whh1 @ h1[cur], layer-1 gates in regs ----
        {
            ull xR[4], xZ[4], xN[4], hR[4], hZ[4], hN[4];
            {
                ull p1 = dup2(cxr), p2 = dup2(cxz), p3 = dup2(cxn);
                ull p4 = dup2(chr), p5 = dup2(chz), p6 = dup2(chn);
                #pragma unroll
                for (int p = 0; p < 4; p++) {
                    xR[p] = p1; xZ[p] = p2; xN[p] = p3;
                    hR[p] = p4; hZ[p] = p5; hN[p] = p6;
                }
            }
            #pragma unroll 4
            for (int k = 0; k < Hh; k++) {
                ull wir = dup2(s->Wt1i[k][j]);
                ull wiz = dup2(s->Wt1i[k][j + 64]);
                ull win = dup2(s->Wt1i[k][j + 128]);
                ull whr = dup2(s->Wt1h[k][j]);
                ull whz = dup2(s->Wt1h[k][j + 64]);
                ull whn = dup2(s->Wt1h[k][j + 128]);
                ulonglong2 g0a = *(const ulonglong2*)&s->h0[nxt][k][bb];
                ulonglong2 g0b = *(const ulonglong2*)&s->h0[nxt][k][bb + 4];
                ulonglong2 g1a = *(const ulonglong2*)&s->h1[cur][k][bb];
                ulonglong2 g1b = *(const ulonglong2*)&s->h1[cur][k][bb + 4];
                fma2(xR[0], wir, g0a.x); fma2(xR[1], wir, g0a.y);
                fma2(xR[2], wir, g0b.x); fma2(xR[3], wir, g0b.y);
                fma2(xZ[0], wiz, g0a.x); fma2(xZ[1], wiz, g0a.y);
                fma2(xZ[2], wiz, g0b.x); fma2(xZ[3], wiz, g0b.y);
                fma2(xN[0], win, g0a.x); fma2(xN[1], win, g0a.y);
                fma2(xN[2], win, g0b.x); fma2(xN[3], win, g0b.y);
                fma2(hR[0], whr, g1a.x); fma2(hR[1], whr, g1a.y);
                fma2(hR[2], whr, g1b.x); fma2(hR[3], whr, g1b.y);
                fma2(hZ[0], whz, g1a.x); fma2(hZ[1], whz, g1a.y);
                fma2(hZ[2], whz, g1b.x); fma2(hZ[3], whz, g1b.y);
                fma2(hN[0], whn, g1a.x); fma2(hN[1], whn, g1a.y);
                fma2(hN[2], whn, g1b.x); fma2(hN[3], whn, g1b.y);
            }
            ulonglong2 hoa = *(const ulonglong2*)&s->h1[cur][j][bb];
            ulonglong2 hob = *(const ulonglong2*)&s->h1[cur][j][bb + 4];
            ull hold[4] = { hoa.x, hoa.y, hob.x, hob.y };
            float hnew[8];
            #pragma unroll
            for (int p = 0; p < 4; p++) {
                float xr0, xr1, xz0, xz1, xn0, xn1;
                float hr0, hr1, hz0, hz1, hn0, hn1, ho0, ho1;
                upk2(xR[p], xr0, xr1); upk2(xZ[p], xz0, xz1); upk2(xN[p], xn0, xn1);
                upk2(hR[p], hr0, hr1); upk2(hZ[p], hz0, hz1); upk2(hN[p], hn0, hn1);
                upk2(hold[p], ho0, ho1);
                float r0 = sigm(xr0 + hr0), z0 = sigm(xz0 + hz0);
                float n0 = tanh_(fmaf(r0, hn0, xn0));
                float r1 = sigm(xr1 + hr1), z1 = sigm(xz1 + hz1);
                float n1 = tanh_(fmaf(r1, hn1, xn1));
                hnew[2*p]     = n0 + z0 * (ho0 - n0);
                hnew[2*p + 1] = n1 + z1 * (ho1 - n1);
            }
            *(float4*)&s->h1[nxt][j][bb]     = make_float4(hnew[0], hnew[1], hnew[2], hnew[3]);
            *(float4*)&s->h1[nxt][j][bb + 4] = make_float4(hnew[4], hnew[5], hnew[6], hnew[7]);
        }
        gbar(barid);
    }

    __syncthreads();

    // ---- final projection: final states live in buffer 0 (Tt even) ----
    if (tid < BT) {
        float acc = bp[0];
        #pragma unroll 8
        for (int k = 0; k < Hh; k++) acc = fmaf(Wp[k],      s->h0[0][k][tid], acc);
        #pragma unroll 8
        for (int k = 0; k < Hh; k++) acc = fmaf(Wp[64 + k], s->h1[0][k][tid], acc);
        out[b0 + tid] = acc;
    }
}

extern "C" void kernel_launch(void* const* d_in, const int* in_sizes, int n_in,
                              void* d_out, int out_size)
{
    const float* x    = (const float*)d_in[0];
    const float* Wih0 = (const float*)d_in[1];
    const float* Whh0 = (const float*)d_in[2];
    const float* bih0 = (const float*)d_in[3];
    const float* bhh0 = (const float*)d_in[4];
    const float* Wih1 = (const float*)d_in[5];
    const float* Whh1 = (const float*)d_in[6];
    const float* bih1 = (const float*)d_in[7];
    const float* bhh1 = (const float*)d_in[8];
    const float* Wp   = (const float*)d_in[9];
    const float* bp   = (const float*)d_in[10];
    float* out = (float*)d_out;

    cudaFuncSetAttribute(gru2_kernel,
                         cudaFuncAttributeMaxDynamicSharedMemorySize,
                         (int)sizeof(Smem));
    gru2_kernel<<<NCTA, NTHR, sizeof(Smem)>>>(
        x, Wih0, Whh0, bih0, bhh0, Wih1, Whh1, bih1, bhh1, Wp, bp, out);
}